// round 1
// baseline (speedup 1.0000x reference)
#include <cuda_runtime.h>
#include <math.h>

// Problem constants (fixed by dataset)
#define B_   4
#define C_   128
#define E_   128
#define H_   4
#define HD_  32
#define G_   8
#define CG_  16          // channels per group
#define EPS_ 1e-5f
#define SCALE_ 0.17677669529663687f   // 32^-0.5
#define MAXN 131072

// ---------------- device scratch (no allocations allowed) ----------------
__device__ double g_gsum [B_*G_];
__device__ double g_gsumsq[B_*G_];
__device__ float  g_qk [B_*H_*C_];   // scale-folded q·Wk coefficients
__device__ float  g_qkb[B_*H_];
__device__ float  g_A  [B_*H_*C_];   // GN-folded logits coefficients
__device__ float  g_Kc [B_*H_];
__device__ float  g_mu [B_*G_];
__device__ float  g_rstd[B_*G_];
__device__ float  g_w  [B_*H_*MAXN];         // logits, then softmax weights (in place)
__device__ float  g_pm [B_*(MAXN/1024)*H_];  // per-tile softmax partial max
__device__ float  g_ps [B_*(MAXN/1024)*H_];  // per-tile softmax partial sumexp
__device__ float  g_M  [B_*H_];
__device__ float  g_Z  [B_*H_];
__device__ double g_s  [B_*H_*C_];           // attn-weighted raw channel sums

// ---------------- kernel 1: zero scratch + LN + q + qk ----------------
__global__ void k_prep(const float* __restrict__ ev, const float* __restrict__ ln_g,
                       const float* __restrict__ ln_b, const float* __restrict__ Wq,
                       const float* __restrict__ bq, const float* __restrict__ Wk,
                       const float* __restrict__ bk)
{
    __shared__ float red[128];
    __shared__ float s_eln[B_][E_];
    __shared__ float s_q[B_][C_];
    int t = threadIdx.x;    // 128 threads

    if (t < B_*G_) { g_gsum[t] = 0.0; g_gsumsq[t] = 0.0; }
    for (int i = t; i < B_*H_*C_; i += 128) g_s[i] = 0.0;

    // LayerNorm of evolution_feat, per batch row
    for (int b = 0; b < B_; b++) {
        float v = ev[b*E_ + t];
        red[t] = v; __syncthreads();
        for (int o = 64; o > 0; o >>= 1) { if (t < o) red[t] += red[t+o]; __syncthreads(); }
        float mu = red[0] / E_; __syncthreads();
        float dv = v - mu;
        red[t] = dv*dv; __syncthreads();
        for (int o = 64; o > 0; o >>= 1) { if (t < o) red[t] += red[t+o]; __syncthreads(); }
        float var = red[0] / E_; __syncthreads();
        s_eln[b][t] = dv * rsqrtf(var + EPS_) * ln_g[t] + ln_b[t];
    }
    __syncthreads();

    // q[b, co] = e_ln[b] . Wq[co] + bq[co]
    for (int b = 0; b < B_; b++) {
        float acc = bq[t];
        #pragma unroll 8
        for (int e = 0; e < E_; e++) acc += s_eln[b][e] * Wq[t*E_ + e];
        s_q[b][t] = acc;
    }
    __syncthreads();

    // qk[b,h,c] = sum_d q[b,h,d] * Wk[h*hd+d, c]   (scale folded in)
    int c = t;
    for (int b = 0; b < B_; b++)
        for (int h = 0; h < H_; h++) {
            float acc = 0.f;
            #pragma unroll 8
            for (int d = 0; d < HD_; d++)
                acc += s_q[b][h*HD_ + d] * Wk[(h*HD_ + d)*C_ + c];
            g_qk[(b*H_ + h)*C_ + c] = acc * SCALE_;
        }
    if (t < B_*H_) {
        int b = t / H_, h = t % H_;
        float acc = 0.f;
        for (int d = 0; d < HD_; d++) acc += s_q[b][h*HD_ + d] * bk[h*HD_ + d];
        g_qkb[t] = acc * SCALE_;
    }
}

// ---------------- kernel 2: group-norm statistics (pass 1 over x) ----------------
__global__ void k_stats(const float* __restrict__ x, int N)
{
    int b = blockIdx.z, c = blockIdx.y;
    long base = ((long)(b*C_ + c))*N + (long)blockIdx.x * 8192;
    const float4* p = (const float4*)(x + base);
    float s = 0.f, ss = 0.f;
    #pragma unroll
    for (int i = 0; i < 8; i++) {
        float4 v = p[threadIdx.x + i*256];
        s  += (v.x + v.y) + (v.z + v.w);
        ss += v.x*v.x + v.y*v.y + v.z*v.z + v.w*v.w;
    }
    double ds = s, dss = ss;
    for (int o = 16; o > 0; o >>= 1) {
        ds  += __shfl_down_sync(0xffffffffu, ds,  o);
        dss += __shfl_down_sync(0xffffffffu, dss, o);
    }
    __shared__ double shs[8], shss[8];
    int w = threadIdx.x >> 5, l = threadIdx.x & 31;
    if (l == 0) { shs[w] = ds; shss[w] = dss; }
    __syncthreads();
    if (threadIdx.x == 0) {
        double a = 0.0, q = 0.0;
        for (int i = 0; i < 8; i++) { a += shs[i]; q += shss[i]; }
        atomicAdd(&g_gsum  [b*G_ + c/CG_], a);
        atomicAdd(&g_gsumsq[b*G_ + c/CG_], q);
    }
}

// ---------------- kernel 3: finalize stats, fold into logits coefficients ----------------
__global__ void k_finalize(const float* __restrict__ gn_g, const float* __restrict__ gn_b, int N)
{
    __shared__ float smu[B_*G_], srs[B_*G_];
    int t = threadIdx.x;   // 128
    if (t < B_*G_) {
        double cnt = (double)CG_ * (double)N;
        double mu  = g_gsum[t] / cnt;
        double var = g_gsumsq[t] / cnt - mu*mu;
        smu[t] = (float)mu;
        srs[t] = rsqrtf((float)var + EPS_);
        g_mu[t] = smu[t]; g_rstd[t] = srs[t];
    }
    __syncthreads();
    int c = t;
    float gg = gn_g[c];
    for (int b = 0; b < B_; b++) {
        float rs = srs[b*G_ + c/CG_];
        for (int h = 0; h < H_; h++) {
            float qk = g_qk[(b*H_ + h)*C_ + c];
            g_A[(b*H_ + h)*C_ + c] = qk * gg * rs;
        }
    }
    __syncthreads();
    if (t < B_*H_) {
        int b = t / H_;
        float acc = g_qkb[t];
        for (int c2 = 0; c2 < C_; c2++) {
            float rs = srs[b*G_ + c2/CG_], mu = smu[b*G_ + c2/CG_];
            acc += g_qk[t*C_ + c2] * (gn_b[c2] - mu*rs*gn_g[c2]);
        }
        g_Kc[t] = acc;
    }
}

// online-softmax pair merge
__device__ __forceinline__ void sm_merge(float& m, float& s, float m2, float s2)
{
    float nm = fmaxf(m, m2);
    s = s * __expf(m - nm) + s2 * __expf(m2 - nm);
    m = nm;
}

// ---------------- kernel 4: logits + online softmax partials (pass 2 over x) ----------------
__global__ void k_logits(const float* __restrict__ x, int N)
{
    int b = blockIdx.y;
    int t = threadIdx.x;   // 256
    __shared__ float sA[H_][C_];
    __shared__ float sKc[H_];
    for (int i = t; i < H_*C_; i += 256) sA[i / C_][i % C_] = g_A[b*H_*C_ + i];
    if (t < H_) sKc[t] = g_Kc[b*H_ + t];
    __syncthreads();

    long n = (long)blockIdx.x * 1024 + t*4;
    const float* xb = x + (long)b*C_*N + n;
    float4 acc[H_];
    #pragma unroll
    for (int h = 0; h < H_; h++) acc[h] = make_float4(0.f, 0.f, 0.f, 0.f);

    #pragma unroll 4
    for (int c = 0; c < C_; c++) {
        float4 v = *(const float4*)(xb + (long)c*N);
        #pragma unroll
        for (int h = 0; h < H_; h++) {
            float a = sA[h][c];
            acc[h].x += a*v.x; acc[h].y += a*v.y;
            acc[h].z += a*v.z; acc[h].w += a*v.w;
        }
    }

    float m[H_], s[H_];
    #pragma unroll
    for (int h = 0; h < H_; h++) {
        float4 l = acc[h];
        float kc = sKc[h];
        l.x += kc; l.y += kc; l.z += kc; l.w += kc;
        *(float4*)(&g_w[(long)(b*H_ + h)*N + n]) = l;
        float mm = fmaxf(fmaxf(l.x, l.y), fmaxf(l.z, l.w));
        s[h] = __expf(l.x - mm) + __expf(l.y - mm) + __expf(l.z - mm) + __expf(l.w - mm);
        m[h] = mm;
    }
    // warp merge
    #pragma unroll
    for (int h = 0; h < H_; h++)
        for (int o = 16; o > 0; o >>= 1) {
            float m2 = __shfl_down_sync(0xffffffffu, m[h], o);
            float s2 = __shfl_down_sync(0xffffffffu, s[h], o);
            sm_merge(m[h], s[h], m2, s2);
        }
    __shared__ float wm[8][H_], ws[8][H_];
    int wp = t >> 5;
    if ((t & 31) == 0)
        for (int h = 0; h < H_; h++) { wm[wp][h] = m[h]; ws[wp][h] = s[h]; }
    __syncthreads();
    if (t == 0) {
        for (int h = 0; h < H_; h++) {
            float mm = wm[0][h], ss = ws[0][h];
            for (int i = 1; i < 8; i++) sm_merge(mm, ss, wm[i][h], ws[i][h]);
            long pi = ((long)b*gridDim.x + blockIdx.x)*H_ + h;
            g_pm[pi] = mm; g_ps[pi] = ss;
        }
    }
}

// ---------------- kernel 5: combine softmax partials per (b,h) ----------------
__global__ void k_combine(int ntiles)
{
    int bh = blockIdx.x;           // 16 blocks
    int b = bh / H_, h = bh % H_;
    int t = threadIdx.x;           // 128
    float m = -3.0e38f, s = 0.f;
    for (int i = t; i < ntiles; i += 128)
        sm_merge(m, s, g_pm[((long)b*ntiles + i)*H_ + h], g_ps[((long)b*ntiles + i)*H_ + h]);
    for (int o = 16; o > 0; o >>= 1) {
        float m2 = __shfl_down_sync(0xffffffffu, m, o);
        float s2 = __shfl_down_sync(0xffffffffu, s, o);
        sm_merge(m, s, m2, s2);
    }
    __shared__ float wm[4], ws[4];
    int wp = t >> 5;
    if ((t & 31) == 0) { wm[wp] = m; ws[wp] = s; }
    __syncthreads();
    if (t == 0) {
        for (int i = 1; i < 4; i++) sm_merge(wm[0], ws[0], wm[i], ws[i]);
        g_M[bh] = wm[0]; g_Z[bh] = ws[0];
    }
}

// ---------------- kernel 6: logits -> weights in place ----------------
__global__ void k_weights(int N)
{
    int bh = blockIdx.y;
    float M = g_M[bh], invZ = 1.0f / g_Z[bh];
    long n = (long)blockIdx.x * 1024 + threadIdx.x*4;
    float4* p = (float4*)&g_w[(long)bh*N + n];
    float4 v = *p;
    v.x = __expf(v.x - M) * invZ;
    v.y = __expf(v.y - M) * invZ;
    v.z = __expf(v.z - M) * invZ;
    v.w = __expf(v.w - M) * invZ;
    *p = v;
}

// ---------------- kernel 7: weighted channel sums (pass 3 over x) ----------------
__global__ void k_passc(const float* __restrict__ x, int N)
{
    int b  = blockIdx.z;
    int c0 = blockIdx.x * 8;           // 8 channels per block (amortize w loads)
    long n0 = (long)blockIdx.y * 2048;
    int t = threadIdx.x;               // 256
    long n = n0 + t*4;

    float4 w0[H_], w1[H_];
    #pragma unroll
    for (int h = 0; h < H_; h++) {
        const float* wb = &g_w[(long)(b*H_ + h)*N];
        w0[h] = *(const float4*)(wb + n);
        w1[h] = *(const float4*)(wb + n + 1024);
    }

    float acc[8][H_];
    #pragma unroll
    for (int ci = 0; ci < 8; ci++)
        #pragma unroll
        for (int h = 0; h < H_; h++) acc[ci][h] = 0.f;

    #pragma unroll
    for (int ci = 0; ci < 8; ci++) {
        const float* xb = x + ((long)(b*C_ + c0 + ci))*N + n;
        float4 v0 = *(const float4*)xb;
        float4 v1 = *(const float4*)(xb + 1024);
        #pragma unroll
        for (int h = 0; h < H_; h++) {
            acc[ci][h] += v0.x*w0[h].x + v0.y*w0[h].y + v0.z*w0[h].z + v0.w*w0[h].w
                        + v1.x*w1[h].x + v1.y*w1[h].y + v1.z*w1[h].z + v1.w*w1[h].w;
        }
    }

    // reduce the 32 per-thread accumulators across the block
    #pragma unroll
    for (int ci = 0; ci < 8; ci++)
        #pragma unroll
        for (int h = 0; h < H_; h++)
            for (int o = 16; o > 0; o >>= 1)
                acc[ci][h] += __shfl_down_sync(0xffffffffu, acc[ci][h], o);

    __shared__ float sred[8][32];
    int wp = t >> 5;
    if ((t & 31) == 0)
        #pragma unroll
        for (int ci = 0; ci < 8; ci++)
            #pragma unroll
            for (int h = 0; h < H_; h++)
                sred[wp][ci*H_ + h] = acc[ci][h];
    __syncthreads();
    if (t < 32) {
        float a = 0.f;
        for (int w = 0; w < 8; w++) a += sred[w][t];
        int ci = t / H_, h = t % H_;
        atomicAdd(&g_s[(b*H_ + h)*C_ + c0 + ci], (double)a);
    }
}

// ---------------- kernel 8: tiny epilogue (Wv, Wo) ----------------
__global__ void k_final(const float* __restrict__ gn_g, const float* __restrict__ gn_b,
                        const float* __restrict__ Wv, const float* __restrict__ bv,
                        const float* __restrict__ Wo, const float* __restrict__ bo,
                        float* __restrict__ out)
{
    int b = blockIdx.x, t = threadIdx.x;   // 4 blocks x 128 threads
    __shared__ float sn[H_][C_];
    __shared__ float ao[C_];

    int c = t;
    int g = c / CG_;
    float mu = g_mu[b*G_ + g], rs = g_rstd[b*G_ + g];
    float gg = gn_g[c], gb = gn_b[c];
    for (int h = 0; h < H_; h++) {
        float s = (float)g_s[(b*H_ + h)*C_ + c];
        sn[h][c] = gg * rs * (s - mu) + gb;     // sum of attn weights == 1
    }
    __syncthreads();

    int o = t, h = o / HD_;
    float acc = bv[o];
    #pragma unroll 8
    for (int c2 = 0; c2 < C_; c2++) acc += Wv[o*C_ + c2] * sn[h][c2];
    ao[o] = acc;
    __syncthreads();

    float y = bo[t];
    #pragma unroll 8
    for (int o2 = 0; o2 < C_; o2++) y += Wo[t*C_ + o2] * ao[o2];
    out[b*C_ + t] = y;
}

// ---------------- launch ----------------
extern "C" void kernel_launch(void* const* d_in, const int* in_sizes, int n_in,
                              void* d_out, int out_size)
{
    const float* x    = (const float*)d_in[0];   // diff_spatial (B,C,d,h,w)
    const float* ev   = (const float*)d_in[1];   // evolution_feat (B,E)
    const float* ln_g = (const float*)d_in[2];
    const float* ln_b = (const float*)d_in[3];
    const float* gn_g = (const float*)d_in[4];
    const float* gn_b = (const float*)d_in[5];
    const float* Wq   = (const float*)d_in[6];
    const float* bq   = (const float*)d_in[7];
    const float* Wk   = (const float*)d_in[8];
    const float* bk   = (const float*)d_in[9];
    const float* Wv   = (const float*)d_in[10];
    const float* bv   = (const float*)d_in[11];
    const float* Wo   = (const float*)d_in[12];
    const float* bo   = (const float*)d_in[13];

    int N = in_sizes[0] / (B_ * C_);   // 131072 for this dataset
    int ntiles = N / 1024;

    k_prep<<<1, 128>>>(ev, ln_g, ln_b, Wq, bq, Wk, bk);
    k_stats<<<dim3(N/8192, C_, B_), 256>>>(x, N);
    k_finalize<<<1, 128>>>(gn_g, gn_b, N);
    k_logits<<<dim3(ntiles, B_), 256>>>(x, N);
    k_combine<<<B_*H_, 128>>>(ntiles);
    k_weights<<<dim3(ntiles, B_*H_), 256>>>(N);
    k_passc<<<dim3(C_/8, N/2048, B_), 256>>>(x, N);
    k_final<<<B_, 128>>>(gn_g, gn_b, Wv, bv, Wo, bo, (float*)d_out);
}

// round 11
// speedup vs baseline: 1.3797x; 1.3797x over previous
#include <cuda_runtime.h>
#include <math.h>

// Problem constants (fixed by dataset)
#define B_   4
#define C_   128
#define E_   128
#define H_   4
#define HD_  32
#define G_   8
#define CG_  16          // channels per group
#define EPS_ 1e-5f
#define SCALE_ 0.17677669529663687f   // 32^-0.5
#define MAXN 131072

// ---------------- device scratch (no allocations allowed) ----------------
__device__ double g_gsum [B_*G_];
__device__ double g_gsumsq[B_*G_];
__device__ float  g_qk  [B_*H_*C_];   // scale-folded q.Wk coefficients
__device__ float  g_qkgg[B_*H_*C_];   // qk * gn_g (rs factored out per group)
__device__ float  g_qkb [B_*H_];
__device__ float  g_Kc  [B_*H_];
__device__ float  g_mu  [B_*G_];
__device__ float  g_rstd[B_*G_];
__device__ float  g_Lhg [B_*H_*G_*MAXN];     // per-group partial logits (67MB)
__device__ float  g_w   [B_*H_*MAXN];        // logits (softmax applied inline later)
__device__ float  g_pm  [B_*(MAXN/1024)*H_]; // per-tile softmax partial max
__device__ float  g_ps  [B_*(MAXN/1024)*H_]; // per-tile softmax partial sumexp
__device__ float  g_M   [B_*H_];
__device__ float  g_Z   [B_*H_];
__device__ float  g_s   [B_*H_*C_];          // attn-weighted raw channel sums

// ---------------- kernel 1: zero scratch + LN + q + qk (one block per batch) ----------------
__global__ void k_prep(const float* __restrict__ ev, const float* __restrict__ ln_g,
                       const float* __restrict__ ln_b, const float* __restrict__ Wq,
                       const float* __restrict__ bq, const float* __restrict__ Wk,
                       const float* __restrict__ bk, const float* __restrict__ gn_g)
{
    __shared__ float red[128];
    __shared__ float s_eln[E_];
    __shared__ float s_q[C_];
    int b = blockIdx.x;
    int t = threadIdx.x;    // 128 threads

    // zero this batch's accumulators
    if (t < G_) { g_gsum[b*G_ + t] = 0.0; g_gsumsq[b*G_ + t] = 0.0; }
    for (int i = t; i < H_*C_; i += 128) g_s[b*H_*C_ + i] = 0.f;

    // LayerNorm of evolution_feat row b
    float v = ev[b*E_ + t];
    red[t] = v; __syncthreads();
    for (int o = 64; o > 0; o >>= 1) { if (t < o) red[t] += red[t+o]; __syncthreads(); }
    float mu = red[0] / E_; __syncthreads();
    float dv = v - mu;
    red[t] = dv*dv; __syncthreads();
    for (int o = 64; o > 0; o >>= 1) { if (t < o) red[t] += red[t+o]; __syncthreads(); }
    float var = red[0] / E_; __syncthreads();
    s_eln[t] = dv * rsqrtf(var + EPS_) * ln_g[t] + ln_b[t];
    __syncthreads();

    // q[co] = e_ln . Wq[co] + bq[co]
    {
        float acc = bq[t];
        #pragma unroll 8
        for (int e = 0; e < E_; e++) acc += s_eln[e] * Wq[t*E_ + e];
        s_q[t] = acc;
    }
    __syncthreads();

    // qk[h,c] = sum_d q[h*hd+d] * Wk[h*hd+d, c]   (scale folded in)
    int c = t;
    float gg = gn_g[c];
    for (int h = 0; h < H_; h++) {
        float acc = 0.f;
        #pragma unroll 8
        for (int d = 0; d < HD_; d++)
            acc += s_q[h*HD_ + d] * Wk[(h*HD_ + d)*C_ + c];
        acc *= SCALE_;
        g_qk  [(b*H_ + h)*C_ + c] = acc;
        g_qkgg[(b*H_ + h)*C_ + c] = acc * gg;
    }
    if (t < H_) {
        float acc = 0.f;
        for (int d = 0; d < HD_; d++) acc += s_q[t*HD_ + d] * bk[t*HD_ + d];
        g_qkb[b*H_ + t] = acc * SCALE_;
    }
}

// ---------------- kernel 2: pass 1 over x — GN stats + per-group partial logits ----------------
// grid (N/2048, G, B), 256 threads; each thread handles 2 float4s (n, n+1024)
__global__ void __launch_bounds__(256) k_pass1(const float* __restrict__ x, int N)
{
    int b = blockIdx.z, g = blockIdx.y;
    int t = threadIdx.x;
    __shared__ float sc[H_][CG_];
    if (t < H_*CG_) sc[t / CG_][t % CG_] = g_qkgg[(b*H_ + t/CG_)*C_ + g*CG_ + (t % CG_)];
    __syncthreads();

    long n = (long)blockIdx.x * 2048 + t*4;
    const float* xb = x + ((long)(b*C_ + g*CG_))*N + n;

    float4 acc0[H_], acc1[H_];
    #pragma unroll
    for (int h = 0; h < H_; h++) {
        acc0[h] = make_float4(0.f,0.f,0.f,0.f);
        acc1[h] = make_float4(0.f,0.f,0.f,0.f);
    }
    float s = 0.f, ss = 0.f;

    #pragma unroll 4
    for (int ci = 0; ci < CG_; ci++) {
        const float* xc = xb + (long)ci*N;
        float4 v0 = *(const float4*)xc;
        float4 v1 = *(const float4*)(xc + 1024);
        s  += (v0.x + v0.y) + (v0.z + v0.w) + (v1.x + v1.y) + (v1.z + v1.w);
        ss += v0.x*v0.x + v0.y*v0.y + v0.z*v0.z + v0.w*v0.w
            + v1.x*v1.x + v1.y*v1.y + v1.z*v1.z + v1.w*v1.w;
        #pragma unroll
        for (int h = 0; h < H_; h++) {
            float a = sc[h][ci];
            acc0[h].x += a*v0.x; acc0[h].y += a*v0.y; acc0[h].z += a*v0.z; acc0[h].w += a*v0.w;
            acc1[h].x += a*v1.x; acc1[h].y += a*v1.y; acc1[h].z += a*v1.z; acc1[h].w += a*v1.w;
        }
    }

    // write partial logits
    #pragma unroll
    for (int h = 0; h < H_; h++) {
        float* Lb = &g_Lhg[(((long)(b*H_ + h))*G_ + g)*N + n];
        *(float4*)Lb = acc0[h];
        *(float4*)(Lb + 1024) = acc1[h];
    }

    // block-reduce stats
    double ds = s, dss = ss;
    for (int o = 16; o > 0; o >>= 1) {
        ds  += __shfl_down_sync(0xffffffffu, ds,  o);
        dss += __shfl_down_sync(0xffffffffu, dss, o);
    }
    __shared__ double shs[8], shss[8];
    int wp = t >> 5, l = t & 31;
    if (l == 0) { shs[wp] = ds; shss[wp] = dss; }
    __syncthreads();
    if (t == 0) {
        double a = 0.0, q = 0.0;
        for (int i = 0; i < 8; i++) { a += shs[i]; q += shss[i]; }
        atomicAdd(&g_gsum  [b*G_ + g], a);
        atomicAdd(&g_gsumsq[b*G_ + g], q);
    }
}

// ---------------- kernel 3: finalize stats + Kc ----------------
__global__ void k_finalize(const float* __restrict__ gn_g, const float* __restrict__ gn_b, int N)
{
    __shared__ float smu[B_*G_], srs[B_*G_];
    int t = threadIdx.x;   // 128
    if (t < B_*G_) {
        double cnt = (double)CG_ * (double)N;
        double mu  = g_gsum[t] / cnt;
        double var = g_gsumsq[t] / cnt - mu*mu;
        smu[t] = (float)mu;
        srs[t] = rsqrtf((float)var + EPS_);
        g_mu[t] = smu[t]; g_rstd[t] = srs[t];
    }
    __syncthreads();
    if (t < B_*H_) {
        int b = t / H_;
        float acc = g_qkb[t];
        for (int c2 = 0; c2 < C_; c2++) {
            float rs = srs[b*G_ + c2/CG_], mu = smu[b*G_ + c2/CG_];
            acc += g_qk[t*C_ + c2] * (gn_b[c2] - mu*rs*gn_g[c2]);
        }
        g_Kc[t] = acc;
    }
}

// online-softmax pair merge
__device__ __forceinline__ void sm_merge(float& m, float& s, float m2, float s2)
{
    float nm = fmaxf(m, m2);
    s = s * __expf(m - nm) + s2 * __expf(m2 - nm);
    m = nm;
}

// ---------------- kernel 4: logits from Lhg + online softmax partials ----------------
// grid (N/1024, B), 256 threads, 1 float4 each
__global__ void __launch_bounds__(256) k_logits2(int N)
{
    int b = blockIdx.y;
    int t = threadIdx.x;
    __shared__ float srs[G_];
    __shared__ float sKc[H_];
    if (t < G_) srs[t] = g_rstd[b*G_ + t];
    if (t < H_) sKc[t] = g_Kc[b*H_ + t];
    __syncthreads();

    long n = (long)blockIdx.x * 1024 + t*4;
    const float* __restrict__ Lb0 = &g_Lhg[((long)(b*H_))*G_*N + n];
    float m[H_], s[H_];
    #pragma unroll
    for (int h = 0; h < H_; h++) {
        float4 acc = make_float4(sKc[h], sKc[h], sKc[h], sKc[h]);
        #pragma unroll
        for (int g = 0; g < G_; g++) {
            float4 v = *(const float4*)(Lb0 + ((long)h*G_ + g)*N);
            float r = srs[g];
            acc.x += r*v.x; acc.y += r*v.y; acc.z += r*v.z; acc.w += r*v.w;
        }
        *(float4*)(&g_w[(long)(b*H_ + h)*N + n]) = acc;
        float mm = fmaxf(fmaxf(acc.x, acc.y), fmaxf(acc.z, acc.w));
        s[h] = __expf(acc.x - mm) + __expf(acc.y - mm) + __expf(acc.z - mm) + __expf(acc.w - mm);
        m[h] = mm;
    }
    #pragma unroll
    for (int h = 0; h < H_; h++)
        for (int o = 16; o > 0; o >>= 1) {
            float m2 = __shfl_down_sync(0xffffffffu, m[h], o);
            float s2 = __shfl_down_sync(0xffffffffu, s[h], o);
            sm_merge(m[h], s[h], m2, s2);
        }
    __shared__ float wm[8][H_], ws[8][H_];
    int wp = t >> 5;
    if ((t & 31) == 0)
        for (int h = 0; h < H_; h++) { wm[wp][h] = m[h]; ws[wp][h] = s[h]; }
    __syncthreads();
    if (t == 0) {
        for (int h = 0; h < H_; h++) {
            float mm = wm[0][h], ss = ws[0][h];
            for (int i = 1; i < 8; i++) sm_merge(mm, ss, wm[i][h], ws[i][h]);
            long pi = ((long)b*gridDim.x + blockIdx.x)*H_ + h;
            g_pm[pi] = mm; g_ps[pi] = ss;
        }
    }
}

// ---------------- kernel 5: combine softmax partials per (b,h) ----------------
__global__ void k_combine(int ntiles)
{
    int bh = blockIdx.x;           // 16 blocks
    int b = bh / H_, h = bh % H_;
    int t = threadIdx.x;           // 128
    float m = -3.0e38f, s = 0.f;
    for (int i = t; i < ntiles; i += 128)
        sm_merge(m, s, g_pm[((long)b*ntiles + i)*H_ + h], g_ps[((long)b*ntiles + i)*H_ + h]);
    for (int o = 16; o > 0; o >>= 1) {
        float m2 = __shfl_down_sync(0xffffffffu, m, o);
        float s2 = __shfl_down_sync(0xffffffffu, s, o);
        sm_merge(m, s, m2, s2);
    }
    __shared__ float wm[4], ws[4];
    int wp = t >> 5;
    if ((t & 31) == 0) { wm[wp] = m; ws[wp] = s; }
    __syncthreads();
    if (t == 0) {
        for (int i = 1; i < 4; i++) sm_merge(wm[0], ws[0], wm[i], ws[i]);
        g_M[bh] = wm[0]; g_Z[bh] = ws[0];
    }
}

// ---------------- kernel 6: weighted channel sums (softmax applied inline) ----------------
// grid (C/8, N/8192, B), 256 threads; n-span 8192 per block (8 iterations)
__global__ void __launch_bounds__(256) k_passc(const float* __restrict__ x, int N)
{
    int b  = blockIdx.z;
    int c0 = blockIdx.x * 8;
    long n0 = (long)blockIdx.y * 8192;
    int t = threadIdx.x;

    __shared__ float sM[H_], sIZ[H_];
    if (t < H_) { sM[t] = g_M[b*H_ + t]; sIZ[t] = 1.0f / g_Z[b*H_ + t]; }
    __syncthreads();

    float acc[8][H_];
    #pragma unroll
    for (int ci = 0; ci < 8; ci++)
        #pragma unroll
        for (int h = 0; h < H_; h++) acc[ci][h] = 0.f;

    #pragma unroll 2
    for (int it = 0; it < 8; it++) {
        long n = n0 + it*1024 + t*4;
        float4 w[H_];
        #pragma unroll
        for (int h = 0; h < H_; h++) {
            float4 l = *(const float4*)&g_w[(long)(b*H_ + h)*N + n];
            float M = sM[h], iz = sIZ[h];
            w[h].x = __expf(l.x - M) * iz;
            w[h].y = __expf(l.y - M) * iz;
            w[h].z = __expf(l.z - M) * iz;
            w[h].w = __expf(l.w - M) * iz;
        }
        #pragma unroll
        for (int ci = 0; ci < 8; ci++) {
            float4 v = *(const float4*)(x + ((long)(b*C_ + c0 + ci))*N + n);
            #pragma unroll
            for (int h = 0; h < H_; h++)
                acc[ci][h] += v.x*w[h].x + v.y*w[h].y + v.z*w[h].z + v.w*w[h].w;
        }
    }

    // reduce 32 per-thread accumulators across the block
    #pragma unroll
    for (int ci = 0; ci < 8; ci++)
        #pragma unroll
        for (int h = 0; h < H_; h++)
            for (int o = 16; o > 0; o >>= 1)
                acc[ci][h] += __shfl_down_sync(0xffffffffu, acc[ci][h], o);

    __shared__ float sred[8][32];
    int wp = t >> 5;
    if ((t & 31) == 0)
        #pragma unroll
        for (int ci = 0; ci < 8; ci++)
            #pragma unroll
            for (int h = 0; h < H_; h++)
                sred[wp][ci*H_ + h] = acc[ci][h];
    __syncthreads();
    if (t < 32) {
        float a = 0.f;
        #pragma unroll
        for (int w = 0; w < 8; w++) a += sred[w][t];
        int ci = t / H_, h = t % H_;
        atomicAdd(&g_s[(b*H_ + h)*C_ + c0 + ci], a);
    }
}

// ---------------- kernel 7: tiny epilogue (Wv, Wo) ----------------
__global__ void k_final(const float* __restrict__ gn_g, const float* __restrict__ gn_b,
                        const float* __restrict__ Wv, const float* __restrict__ bv,
                        const float* __restrict__ Wo, const float* __restrict__ bo,
                        float* __restrict__ out)
{
    int b = blockIdx.x, t = threadIdx.x;   // 4 blocks x 128 threads
    __shared__ float sn[H_][C_];
    __shared__ float ao[C_];

    int c = t;
    int g = c / CG_;
    float mu = g_mu[b*G_ + g], rs = g_rstd[b*G_ + g];
    float gg = gn_g[c], gb = gn_b[c];
    for (int h = 0; h < H_; h++) {
        float s = g_s[(b*H_ + h)*C_ + c];
        sn[h][c] = gg * rs * (s - mu) + gb;     // sum of attn weights == 1
    }
    __syncthreads();

    int o = t, h = o / HD_;
    float acc = bv[o];
    #pragma unroll 8
    for (int c2 = 0; c2 < C_; c2++) acc += Wv[o*C_ + c2] * sn[h][c2];
    ao[o] = acc;
    __syncthreads();

    float y = bo[t];
    #pragma unroll 8
    for (int o2 = 0; o2 < C_; o2++) y += Wo[t*C_ + o2] * ao[o2];
    out[b*C_ + t] = y;
}

// ---------------- launch ----------------
extern "C" void kernel_launch(void* const* d_in, const int* in_sizes, int n_in,
                              void* d_out, int out_size)
{
    const float* x    = (const float*)d_in[0];   // diff_spatial (B,C,d,h,w)
    const float* ev   = (const float*)d_in[1];   // evolution_feat (B,E)
    const float* ln_g = (const float*)d_in[2];
    const float* ln_b = (const float*)d_in[3];
    const float* gn_g = (const float*)d_in[4];
    const float* gn_b = (const float*)d_in[5];
    const float* Wq   = (const float*)d_in[6];
    const float* bq   = (const float*)d_in[7];
    const float* Wk   = (const float*)d_in[8];
    const float* bk   = (const float*)d_in[9];
    const float* Wv   = (const float*)d_in[10];
    const float* bv   = (const float*)d_in[11];
    const float* Wo   = (const float*)d_in[12];
    const float* bo   = (const float*)d_in[13];

    int N = in_sizes[0] / (B_ * C_);   // 131072 for this dataset
    int ntiles = N / 1024;

    k_prep<<<B_, 128>>>(ev, ln_g, ln_b, Wq, bq, Wk, bk, gn_g);
    k_pass1<<<dim3(N/2048, G_, B_), 256>>>(x, N);
    k_finalize<<<1, 128>>>(gn_g, gn_b, N);
    k_logits2<<<dim3(ntiles, B_), 256>>>(N);
    k_combine<<<B_*H_, 128>>>(ntiles);
    k_passc<<<dim3(C_/8, N/8192, B_), 256>>>(x, N);
    k_final<<<B_, 128>>>(gn_g, gn_b, Wv, bv, Wo, bo, (float*)d_out);
}

// round 17
// speedup vs baseline: 1.4461x; 1.0481x over previous
#include <cuda_runtime.h>
#include <cuda_bf16.h>
#include <math.h>

// Problem constants (fixed by dataset)
#define B_   4
#define C_   128
#define E_   128
#define H_   4
#define HD_  32
#define G_   8
#define CG_  16          // channels per group
#define EPS_ 1e-5f
#define SCALE_ 0.17677669529663687f   // 32^-0.5
#define MAXN 131072

// ---------------- device scratch (no allocations allowed) ----------------
__device__ double g_gsum [B_*G_];
__device__ double g_gsumsq[B_*G_];
__device__ float  g_qk  [B_*H_*C_];   // scale-folded q.Wk coefficients
__device__ float  g_qkgg[B_*H_*C_];   // qk * gn_g (rs factored out per group)
__device__ float  g_qkb [B_*H_];
__device__ float  g_Kc  [B_*H_];
__device__ float  g_mu  [B_*G_];
__device__ float  g_rstd[B_*G_];
__device__ __nv_bfloat16 g_Lhg[B_*H_*G_*MAXN];  // per-group partial logits (33.5MB, bf16)
__device__ float  g_w   [B_*H_*MAXN];        // logits (softmax applied inline later)
__device__ float  g_pm  [B_*(MAXN/1024)*H_]; // per-tile softmax partial max
__device__ float  g_ps  [B_*(MAXN/1024)*H_]; // per-tile softmax partial sumexp
__device__ float  g_M   [B_*H_];
__device__ float  g_Z   [B_*H_];
__device__ float  g_s   [B_*H_*C_];          // attn-weighted raw channel sums

// ---------------- kernel 1: zero scratch + LN + q + qk (one block per batch) ----------------
__global__ void k_prep(const float* __restrict__ ev, const float* __restrict__ ln_g,
                       const float* __restrict__ ln_b, const float* __restrict__ Wq,
                       const float* __restrict__ bq, const float* __restrict__ Wk,
                       const float* __restrict__ bk, const float* __restrict__ gn_g)
{
    __shared__ float red[128];
    __shared__ float s_eln[E_];
    __shared__ float s_q[C_];
    int b = blockIdx.x;
    int t = threadIdx.x;    // 128 threads

    // zero this batch's accumulators
    if (t < G_) { g_gsum[b*G_ + t] = 0.0; g_gsumsq[b*G_ + t] = 0.0; }
    for (int i = t; i < H_*C_; i += 128) g_s[b*H_*C_ + i] = 0.f;

    // LayerNorm of evolution_feat row b
    float v = ev[b*E_ + t];
    red[t] = v; __syncthreads();
    for (int o = 64; o > 0; o >>= 1) { if (t < o) red[t] += red[t+o]; __syncthreads(); }
    float mu = red[0] / E_; __syncthreads();
    float dv = v - mu;
    red[t] = dv*dv; __syncthreads();
    for (int o = 64; o > 0; o >>= 1) { if (t < o) red[t] += red[t+o]; __syncthreads(); }
    float var = red[0] / E_; __syncthreads();
    s_eln[t] = dv * rsqrtf(var + EPS_) * ln_g[t] + ln_b[t];
    __syncthreads();

    // q[co] = e_ln . Wq[co] + bq[co]
    {
        float acc = bq[t];
        #pragma unroll 8
        for (int e = 0; e < E_; e++) acc += s_eln[e] * Wq[t*E_ + e];
        s_q[t] = acc;
    }
    __syncthreads();

    // qk[h,c] = sum_d q[h*hd+d] * Wk[h*hd+d, c]   (scale folded in)
    int c = t;
    float gg = gn_g[c];
    for (int h = 0; h < H_; h++) {
        float acc = 0.f;
        #pragma unroll 8
        for (int d = 0; d < HD_; d++)
            acc += s_q[h*HD_ + d] * Wk[(h*HD_ + d)*C_ + c];
        acc *= SCALE_;
        g_qk  [(b*H_ + h)*C_ + c] = acc;
        g_qkgg[(b*H_ + h)*C_ + c] = acc * gg;
    }
    if (t < H_) {
        float acc = 0.f;
        for (int d = 0; d < HD_; d++) acc += s_q[t*HD_ + d] * bk[t*HD_ + d];
        g_qkb[b*H_ + t] = acc * SCALE_;
    }
}

// ---------------- kernel 2: pass 1 over x — GN stats + per-group partial logits (bf16) ----------------
// grid (N/2048, G, B), 256 threads; each thread handles 2 float4s (n, n+1024)
__global__ void __launch_bounds__(256) k_pass1(const float* __restrict__ x, int N)
{
    int b = blockIdx.z, g = blockIdx.y;
    int t = threadIdx.x;
    __shared__ float sc[H_][CG_];
    if (t < H_*CG_) sc[t / CG_][t % CG_] = g_qkgg[(b*H_ + t/CG_)*C_ + g*CG_ + (t % CG_)];
    __syncthreads();

    long n = (long)blockIdx.x * 2048 + t*4;
    const float* xb = x + ((long)(b*C_ + g*CG_))*N + n;

    float4 acc0[H_], acc1[H_];
    #pragma unroll
    for (int h = 0; h < H_; h++) {
        acc0[h] = make_float4(0.f,0.f,0.f,0.f);
        acc1[h] = make_float4(0.f,0.f,0.f,0.f);
    }
    float s = 0.f, ss = 0.f;

    #pragma unroll 4
    for (int ci = 0; ci < CG_; ci++) {
        const float* xc = xb + (long)ci*N;
        float4 v0 = *(const float4*)xc;
        float4 v1 = *(const float4*)(xc + 1024);
        s  += (v0.x + v0.y) + (v0.z + v0.w) + (v1.x + v1.y) + (v1.z + v1.w);
        ss += v0.x*v0.x + v0.y*v0.y + v0.z*v0.z + v0.w*v0.w
            + v1.x*v1.x + v1.y*v1.y + v1.z*v1.z + v1.w*v1.w;
        #pragma unroll
        for (int h = 0; h < H_; h++) {
            float a = sc[h][ci];
            acc0[h].x += a*v0.x; acc0[h].y += a*v0.y; acc0[h].z += a*v0.z; acc0[h].w += a*v0.w;
            acc1[h].x += a*v1.x; acc1[h].y += a*v1.y; acc1[h].z += a*v1.z; acc1[h].w += a*v1.w;
        }
    }

    // write partial logits as bf16 (4 values = 8B coalesced store per half)
    #pragma unroll
    for (int h = 0; h < H_; h++) {
        __nv_bfloat16* Lb = &g_Lhg[(((long)(b*H_ + h))*G_ + g)*N + n];
        uint2 u0, u1;
        *reinterpret_cast<__nv_bfloat162*>(&u0.x) = __floats2bfloat162_rn(acc0[h].x, acc0[h].y);
        *reinterpret_cast<__nv_bfloat162*>(&u0.y) = __floats2bfloat162_rn(acc0[h].z, acc0[h].w);
        *reinterpret_cast<__nv_bfloat162*>(&u1.x) = __floats2bfloat162_rn(acc1[h].x, acc1[h].y);
        *reinterpret_cast<__nv_bfloat162*>(&u1.y) = __floats2bfloat162_rn(acc1[h].z, acc1[h].w);
        *reinterpret_cast<uint2*>(Lb)        = u0;
        *reinterpret_cast<uint2*>(Lb + 1024) = u1;
    }

    // block-reduce stats
    double ds = s, dss = ss;
    for (int o = 16; o > 0; o >>= 1) {
        ds  += __shfl_down_sync(0xffffffffu, ds,  o);
        dss += __shfl_down_sync(0xffffffffu, dss, o);
    }
    __shared__ double shs[8], shss[8];
    int wp = t >> 5, l = t & 31;
    if (l == 0) { shs[wp] = ds; shss[wp] = dss; }
    __syncthreads();
    if (t == 0) {
        double a = 0.0, q = 0.0;
        for (int i = 0; i < 8; i++) { a += shs[i]; q += shss[i]; }
        atomicAdd(&g_gsum  [b*G_ + g], a);
        atomicAdd(&g_gsumsq[b*G_ + g], q);
    }
}

// ---------------- kernel 3: finalize stats + Kc ----------------
__global__ void k_finalize(const float* __restrict__ gn_g, const float* __restrict__ gn_b, int N)
{
    __shared__ float smu[B_*G_], srs[B_*G_];
    int t = threadIdx.x;   // 128
    if (t < B_*G_) {
        double cnt = (double)CG_ * (double)N;
        double mu  = g_gsum[t] / cnt;
        double var = g_gsumsq[t] / cnt - mu*mu;
        smu[t] = (float)mu;
        srs[t] = rsqrtf((float)var + EPS_);
        g_mu[t] = smu[t]; g_rstd[t] = srs[t];
    }
    __syncthreads();
    if (t < B_*H_) {
        int b = t / H_;
        float acc = g_qkb[t];
        for (int c2 = 0; c2 < C_; c2++) {
            float rs = srs[b*G_ + c2/CG_], mu = smu[b*G_ + c2/CG_];
            acc += g_qk[t*C_ + c2] * (gn_b[c2] - mu*rs*gn_g[c2]);
        }
        g_Kc[t] = acc;
    }
}

// online-softmax pair merge
__device__ __forceinline__ void sm_merge(float& m, float& s, float m2, float s2)
{
    float nm = fmaxf(m, m2);
    s = s * __expf(m - nm) + s2 * __expf(m2 - nm);
    m = nm;
}

// ---------------- kernel 4: logits from bf16 Lhg + online softmax partials ----------------
// grid (N/1024, B*H), 256 threads, one head per block (occupancy-saturating)
__global__ void __launch_bounds__(256) k_logits2(int N)
{
    int bh = blockIdx.y;
    int b = bh / H_, h = bh % H_;
    int t = threadIdx.x;
    __shared__ float srs[G_];
    __shared__ float sKc;
    if (t < G_) srs[t] = g_rstd[b*G_ + t];
    if (t == 0) sKc = g_Kc[bh];
    __syncthreads();

    long n = (long)blockIdx.x * 1024 + t*4;
    float kc = sKc;
    float4 acc = make_float4(kc, kc, kc, kc);
    #pragma unroll
    for (int g = 0; g < G_; g++) {
        uint2 u = *reinterpret_cast<const uint2*>(&g_Lhg[((long)bh*G_ + g)*N + n]);
        float2 f0 = __bfloat1622float2(*reinterpret_cast<__nv_bfloat162*>(&u.x));
        float2 f1 = __bfloat1622float2(*reinterpret_cast<__nv_bfloat162*>(&u.y));
        float r = srs[g];
        acc.x += r*f0.x; acc.y += r*f0.y; acc.z += r*f1.x; acc.w += r*f1.y;
    }
    *(float4*)(&g_w[(long)bh*N + n]) = acc;

    float m = fmaxf(fmaxf(acc.x, acc.y), fmaxf(acc.z, acc.w));
    float s = __expf(acc.x - m) + __expf(acc.y - m) + __expf(acc.z - m) + __expf(acc.w - m);
    for (int o = 16; o > 0; o >>= 1) {
        float m2 = __shfl_down_sync(0xffffffffu, m, o);
        float s2 = __shfl_down_sync(0xffffffffu, s, o);
        sm_merge(m, s, m2, s2);
    }
    __shared__ float wm[8], ws[8];
    int wp = t >> 5;
    if ((t & 31) == 0) { wm[wp] = m; ws[wp] = s; }
    __syncthreads();
    if (t == 0) {
        float mm = wm[0], sss = ws[0];
        for (int i = 1; i < 8; i++) sm_merge(mm, sss, wm[i], ws[i]);
        long pi = ((long)b*gridDim.x + blockIdx.x)*H_ + h;
        g_pm[pi] = mm; g_ps[pi] = sss;
    }
}

// ---------------- kernel 5: combine softmax partials per (b,h) ----------------
__global__ void k_combine(int ntiles)
{
    int bh = blockIdx.x;           // 16 blocks
    int b = bh / H_, h = bh % H_;
    int t = threadIdx.x;           // 128
    float m = -3.0e38f, s = 0.f;
    for (int i = t; i < ntiles; i += 128)
        sm_merge(m, s, g_pm[((long)b*ntiles + i)*H_ + h], g_ps[((long)b*ntiles + i)*H_ + h]);
    for (int o = 16; o > 0; o >>= 1) {
        float m2 = __shfl_down_sync(0xffffffffu, m, o);
        float s2 = __shfl_down_sync(0xffffffffu, s, o);
        sm_merge(m, s, m2, s2);
    }
    __shared__ float wm[4], ws[4];
    int wp = t >> 5;
    if ((t & 31) == 0) { wm[wp] = m; ws[wp] = s; }
    __syncthreads();
    if (t == 0) {
        for (int i = 1; i < 4; i++) sm_merge(wm[0], ws[0], wm[i], ws[i]);
        g_M[bh] = wm[0]; g_Z[bh] = ws[0];
    }
}

// ---------------- kernel 6: weighted channel sums (softmax applied inline) ----------------
// grid (C/8, N/8192, B), 256 threads; n-span 8192 per block (8 iterations)
__global__ void __launch_bounds__(256) k_passc(const float* __restrict__ x, int N)
{
    int b  = blockIdx.z;
    int c0 = blockIdx.x * 8;
    long n0 = (long)blockIdx.y * 8192;
    int t = threadIdx.x;

    __shared__ float sM[H_], sIZ[H_];
    if (t < H_) { sM[t] = g_M[b*H_ + t]; sIZ[t] = 1.0f / g_Z[b*H_ + t]; }
    __syncthreads();

    float acc[8][H_];
    #pragma unroll
    for (int ci = 0; ci < 8; ci++)
        #pragma unroll
        for (int h = 0; h < H_; h++) acc[ci][h] = 0.f;

    #pragma unroll 2
    for (int it = 0; it < 8; it++) {
        long n = n0 + it*1024 + t*4;
        float4 w[H_];
        #pragma unroll
        for (int h = 0; h < H_; h++) {
            float4 l = *(const float4*)&g_w[(long)(b*H_ + h)*N + n];
            float M = sM[h], iz = sIZ[h];
            w[h].x = __expf(l.x - M) * iz;
            w[h].y = __expf(l.y - M) * iz;
            w[h].z = __expf(l.z - M) * iz;
            w[h].w = __expf(l.w - M) * iz;
        }
        #pragma unroll
        for (int ci = 0; ci < 8; ci++) {
            float4 v = *(const float4*)(x + ((long)(b*C_ + c0 + ci))*N + n);
            #pragma unroll
            for (int h = 0; h < H_; h++)
                acc[ci][h] += v.x*w[h].x + v.y*w[h].y + v.z*w[h].z + v.w*w[h].w;
        }
    }

    // reduce 32 per-thread accumulators across the block
    #pragma unroll
    for (int ci = 0; ci < 8; ci++)
        #pragma unroll
        for (int h = 0; h < H_; h++)
            for (int o = 16; o > 0; o >>= 1)
                acc[ci][h] += __shfl_down_sync(0xffffffffu, acc[ci][h], o);

    __shared__ float sred[8][32];
    int wp = t >> 5;
    if ((t & 31) == 0)
        #pragma unroll
        for (int ci = 0; ci < 8; ci++)
            #pragma unroll
            for (int h = 0; h < H_; h++)
                sred[wp][ci*H_ + h] = acc[ci][h];
    __syncthreads();
    if (t < 32) {
        float a = 0.f;
        #pragma unroll
        for (int w = 0; w < 8; w++) a += sred[w][t];
        int ci = t / H_, h = t % H_;
        atomicAdd(&g_s[(b*H_ + h)*C_ + c0 + ci], a);
    }
}

// ---------------- kernel 7: tiny epilogue (Wv, Wo) ----------------
__global__ void k_final(const float* __restrict__ gn_g, const float* __restrict__ gn_b,
                        const float* __restrict__ Wv, const float* __restrict__ bv,
                        const float* __restrict__ Wo, const float* __restrict__ bo,
                        float* __restrict__ out)
{
    int b = blockIdx.x, t = threadIdx.x;   // 4 blocks x 128 threads
    __shared__ float sn[H_][C_];
    __shared__ float ao[C_];

    int c = t;
    int g = c / CG_;
    float mu = g_mu[b*G_ + g], rs = g_rstd[b*G_ + g];
    float gg = gn_g[c], gb = gn_b[c];
    for (int h = 0; h < H_; h++) {
        float s = g_s[(b*H_ + h)*C_ + c];
        sn[h][c] = gg * rs * (s - mu) + gb;     // sum of attn weights == 1
    }
    __syncthreads();

    int o = t, h = o / HD_;
    float acc = bv[o];
    #pragma unroll 8
    for (int c2 = 0; c2 < C_; c2++) acc += Wv[o*C_ + c2] * sn[h][c2];
    ao[o] = acc;
    __syncthreads();

    float y = bo[t];
    #pragma unroll 8
    for (int o2 = 0; o2 < C_; o2++) y += Wo[t*C_ + o2] * ao[o2];
    out[b*C_ + t] = y;
}

// ---------------- launch ----------------
extern "C" void kernel_launch(void* const* d_in, const int* in_sizes, int n_in,
                              void* d_out, int out_size)
{
    const float* x    = (const float*)d_in[0];   // diff_spatial (B,C,d,h,w)
    const float* ev   = (const float*)d_in[1];   // evolution_feat (B,E)
    const float* ln_g = (const float*)d_in[2];
    const float* ln_b = (const float*)d_in[3];
    const float* gn_g = (const float*)d_in[4];
    const float* gn_b = (const float*)d_in[5];
    const float* Wq   = (const float*)d_in[6];
    const float* bq   = (const float*)d_in[7];
    const float* Wk   = (const float*)d_in[8];
    const float* bk   = (const float*)d_in[9];
    const float* Wv   = (const float*)d_in[10];
    const float* bv   = (const float*)d_in[11];
    const float* Wo   = (const float*)d_in[12];
    const float* bo   = (const float*)d_in[13];

    int N = in_sizes[0] / (B_ * C_);   // 131072 for this dataset
    int ntiles = N / 1024;

    k_prep<<<B_, 128>>>(ev, ln_g, ln_b, Wq, bq, Wk, bk, gn_g);
    k_pass1<<<dim3(N/2048, G_, B_), 256>>>(x, N);
    k_finalize<<<1, 128>>>(gn_g, gn_b, N);
    k_logits2<<<dim3(ntiles, B_*H_), 256>>>(N);
    k_combine<<<B_*H_, 128>>>(ntiles);
    k_passc<<<dim3(C_/8, N/8192, B_), 256>>>(x, N);
    k_final<<<B_, 128>>>(gn_g, gn_b, Wv, bv, Wo, bo, (float*)d_out);
}